// round 1
// baseline (speedup 1.0000x reference)
#include <cuda_runtime.h>

#define TH 16
#define TW 64
#define NT 384
#define HIMG 512
#define WIMG 512

__global__ __launch_bounds__(NT) void jpeg_kernel(
    const float* __restrict__ in, const float* __restrict__ quant,
    const float* __restrict__ dct, float* __restrict__ out)
{
    __shared__ float s_a[3][TH][TW];   // ycbcr (-128 adjusted), later decomp
    __shared__ float s_b[3][TH][TW];   // reconstructed ycbcr2 (with +128 folded for Y)
    __shared__ float s_d[8][8];        // dct matrix
    __shared__ float s_q[192];         // quant table, per channel 8x8

    const int tid = threadIdx.x;
    const int b   = blockIdx.z;
    const int ty0 = blockIdx.y * TH;
    const int tx0 = blockIdx.x * TW;

    // ---- load DCT matrix + build quant table ----
    if (tid < 64) {
        s_d[tid >> 3][tid & 7] = dct[tid];
    } else if (tid < 256) {
        int i = tid - 64;
        float qv = rintf(quant[i] * 255.0f);
        float q1 = rintf((qv * 50.0f + 50.0f) / 100.0f);   // exact fp32 division
        s_q[i] = fminf(fmaxf(q1, 1.0f), 255.0f);
    }

    const size_t plane = (size_t)HIMG * WIMG;
    const float* base  = in  + (size_t)b * 3 * plane;
    float*       obase = out + (size_t)b * 3 * plane;

    // ---- phase 1: RGB -> YCbCr (clipped) into smem ----
    for (int p = tid; p < TH * TW; p += NT) {
        int py = p / TW, px = p % TW;
        size_t idx = (size_t)(ty0 + py) * WIMG + (tx0 + px);
        float r  = 255.0f * base[idx];
        float g  = 255.0f * base[plane + idx];
        float bb = 255.0f * base[2 * plane + idx];
        float y  = fmaf(0.114f, bb, fmaf(0.587f, g, 0.299f * r));
        float cb = fmaf(0.5f,   bb, fmaf(-0.331264108f, g, -0.168735892f * r)) + 128.0f;
        float cr = fmaf(-0.081312411f, bb, fmaf(-0.418687589f, g, 0.5f * r))   + 128.0f;
        s_a[0][py][px] = fminf(fmaxf(y,  0.0f), 255.0f) - 128.0f;
        s_a[1][py][px] = fminf(fmaxf(cb, 0.0f), 255.0f);
        s_a[2][py][px] = fminf(fmaxf(cr, 0.0f), 255.0f);
    }
    __syncthreads();

    // ---- phase 2: chroma 2x2 mean + broadcast, subtract 128 ----
    for (int t = tid; t < (TH/2)*(TW/2)*2; t += NT) {
        int c    = 1 + t / ((TH/2)*(TW/2));
        int cell = t % ((TH/2)*(TW/2));
        int cy   = (cell / (TW/2)) * 2;
        int cx   = (cell % (TW/2)) * 2;
        float m = 0.25f * (((s_a[c][cy][cx] + s_a[c][cy][cx+1]) + s_a[c][cy+1][cx]) + s_a[c][cy+1][cx+1]) - 128.0f;
        s_a[c][cy][cx]     = m;  s_a[c][cy][cx+1]   = m;
        s_a[c][cy+1][cx]   = m;  s_a[c][cy+1][cx+1] = m;
    }
    __syncthreads();

    // ---- block/row assignment: 48 (channel, 8x8-block) units * 8 row-threads ----
    const int blk = tid >> 3;      // 0..47
    const int r   = tid & 7;       // row within 8x8 block
    const int c   = blk >> 4;      // channel 0..2 (16 blocks per channel)
    const int rem = blk & 15;
    const int by  = rem >> 3;      // 0..1  (TH/8)
    const int bx  = rem & 7;       // 0..7  (TW/8)
    const float* qrow = &s_q[(c * 8 + r) * 8];

    // ---- phase 3: DCT + quantize/dequantize ----
    float tmp[8];
    #pragma unroll
    for (int k = 0; k < 8; k++) tmp[k] = 0.0f;
    #pragma unroll
    for (int j = 0; j < 8; j++) {
        float d = s_d[r][j];
        const float4 x0 = *(const float4*)&s_a[c][by*8 + j][bx*8];
        const float4 x1 = *(const float4*)&s_a[c][by*8 + j][bx*8 + 4];
        tmp[0] = fmaf(d, x0.x, tmp[0]);
        tmp[1] = fmaf(d, x0.y, tmp[1]);
        tmp[2] = fmaf(d, x0.z, tmp[2]);
        tmp[3] = fmaf(d, x0.w, tmp[3]);
        tmp[4] = fmaf(d, x1.x, tmp[4]);
        tmp[5] = fmaf(d, x1.y, tmp[5]);
        tmp[6] = fmaf(d, x1.z, tmp[6]);
        tmp[7] = fmaf(d, x1.w, tmp[7]);
    }
    float dec[8];
    #pragma unroll
    for (int l = 0; l < 8; l++) {
        float acc = 0.0f;
        #pragma unroll
        for (int k = 0; k < 8; k++) acc = fmaf(tmp[k], s_d[l][k], acc);
        float q    = qrow[l];
        float comp = rintf(acc / q);
        dec[l]     = rintf(comp * q);
    }
    __syncthreads();   // all reads of s_a done before overwrite
    *(float4*)&s_a[c][by*8 + r][bx*8]     = make_float4(dec[0], dec[1], dec[2], dec[3]);
    *(float4*)&s_a[c][by*8 + r][bx*8 + 4] = make_float4(dec[4], dec[5], dec[6], dec[7]);
    __syncthreads();

    // ---- phase 4: IDCT ----
    #pragma unroll
    for (int k = 0; k < 8; k++) tmp[k] = 0.0f;
    #pragma unroll
    for (int j = 0; j < 8; j++) {
        float d = s_d[j][r];       // D^T
        const float4 x0 = *(const float4*)&s_a[c][by*8 + j][bx*8];
        const float4 x1 = *(const float4*)&s_a[c][by*8 + j][bx*8 + 4];
        tmp[0] = fmaf(d, x0.x, tmp[0]);
        tmp[1] = fmaf(d, x0.y, tmp[1]);
        tmp[2] = fmaf(d, x0.z, tmp[2]);
        tmp[3] = fmaf(d, x0.w, tmp[3]);
        tmp[4] = fmaf(d, x1.x, tmp[4]);
        tmp[5] = fmaf(d, x1.y, tmp[5]);
        tmp[6] = fmaf(d, x1.z, tmp[6]);
        tmp[7] = fmaf(d, x1.w, tmp[7]);
    }
    {
        const float off = (c == 0) ? 128.0f : 0.0f;   // (idct + 128) - channel_offset
        float zr[8];
        #pragma unroll
        for (int l = 0; l < 8; l++) {
            float acc = 0.0f;
            #pragma unroll
            for (int k = 0; k < 8; k++) acc = fmaf(tmp[k], s_d[k][l], acc);
            zr[l] = acc + off;
        }
        *(float4*)&s_b[c][by*8 + r][bx*8]     = make_float4(zr[0], zr[1], zr[2], zr[3]);
        *(float4*)&s_b[c][by*8 + r][bx*8 + 4] = make_float4(zr[4], zr[5], zr[6], zr[7]);
    }
    __syncthreads();

    // ---- phase 5: YCbCr -> RGB, clip, round, store ----
    for (int p = tid; p < TH * TW; p += NT) {
        int py = p / TW, px = p % TW;
        float y  = s_b[0][py][px];
        float cb = s_b[1][py][px];
        float cr = s_b[2][py][px];
        float R = fmaf(1.402f, cr, y);
        float G = fmaf(-0.714136286f, cr, fmaf(-0.344136286f, cb, y));
        float B = fmaf(1.772f, cb, y);
        size_t idx = (size_t)(ty0 + py) * WIMG + (tx0 + px);
        obase[idx]             = rintf(fminf(fmaxf(R, 0.0f), 255.0f)) / 255.0f;
        obase[plane + idx]     = rintf(fminf(fmaxf(G, 0.0f), 255.0f)) / 255.0f;
        obase[2 * plane + idx] = rintf(fminf(fmaxf(B, 0.0f), 255.0f)) / 255.0f;
    }
}

extern "C" void kernel_launch(void* const* d_in, const int* in_sizes, int n_in,
                              void* d_out, int out_size)
{
    const float* x = nullptr;
    const float* q = nullptr;
    const float* d = nullptr;
    int nimg = 0;
    for (int i = 0; i < n_in; i++) {
        if (in_sizes[i] == 192)      q = (const float*)d_in[i];
        else if (in_sizes[i] == 64)  d = (const float*)d_in[i];
        else { x = (const float*)d_in[i]; nimg = in_sizes[i] / (3 * HIMG * WIMG); }
    }
    dim3 grid(WIMG / TW, HIMG / TH, nimg);
    jpeg_kernel<<<grid, NT>>>(x, q, d, (float*)d_out);
}

// round 2
// speedup vs baseline: 1.7377x; 1.7377x over previous
#include <cuda_runtime.h>

#define TH 16
#define TW 64
#define NT 384
#define HIMG 512
#define WIMG 512
#define SAW 68   // padded row stride for s_a (16B-aligned, bank-rotating)

__global__ __launch_bounds__(NT, 4) void jpeg_kernel(
    const float* __restrict__ in, const float* __restrict__ quant,
    const float* __restrict__ dct, float* __restrict__ out)
{
    __shared__ float s_a[3][TH][SAW];  // ycbcr-128 -> decomp -> reconstructed
    __shared__ float s_d[8][9];        // dct matrix (padded)
    __shared__ float s_q[3][8][9];     // quant table (padded)

    const int tid = threadIdx.x;
    const int b   = blockIdx.z;
    const int ty0 = blockIdx.y * TH;
    const int tx0 = blockIdx.x * TW;

    // ---- tables ----
    if (tid < 64) {
        s_d[tid >> 3][tid & 7] = dct[tid];
    } else if (tid < 256) {
        int i = tid - 64;
        float qv = rintf(quant[i] * 255.0f);
        float q1 = rintf((qv * 50.0f + 50.0f) / 100.0f);
        s_q[i >> 6][(i >> 3) & 7][i & 7] = fminf(fmaxf(q1, 1.0f), 255.0f);
    }

    const size_t plane = (size_t)HIMG * WIMG;
    const float* base  = in  + (size_t)b * 3 * plane;
    float*       obase = out + (size_t)b * 3 * plane;

    // ---- phase 1 (fused): RGB->YCbCr + clip + chroma 2x2 mean + (-128) ----
    if (tid < (TH/2) * (TW/2)) {                 // 256 quads
        const int qy = tid >> 5;                 // 0..7
        const int qx = tid & 31;                 // 0..31
        const int py = qy * 2, px = qx * 2;
        const size_t idx = (size_t)(ty0 + py) * WIMG + (tx0 + px);

        float2 r0 = *(const float2*)&base[idx];
        float2 r1 = *(const float2*)&base[idx + WIMG];
        float2 g0 = *(const float2*)&base[plane + idx];
        float2 g1 = *(const float2*)&base[plane + idx + WIMG];
        float2 b0 = *(const float2*)&base[2*plane + idx];
        float2 b1 = *(const float2*)&base[2*plane + idx + WIMG];

        float r00 = 255.0f*r0.x, r01 = 255.0f*r0.y, r10 = 255.0f*r1.x, r11 = 255.0f*r1.y;
        float g00 = 255.0f*g0.x, g01 = 255.0f*g0.y, g10 = 255.0f*g1.x, g11 = 255.0f*g1.y;
        float b00 = 255.0f*b0.x, b01 = 255.0f*b0.y, b10 = 255.0f*b1.x, b11 = 255.0f*b1.y;

        #define YV(R,G,B)  fmaf(0.114f,(B), fmaf(0.587f,(G), 0.299f*(R)))
        #define CBV(R,G,B) (fmaf(0.5f,(B),  fmaf(-0.331264108f,(G), -0.168735892f*(R))) + 128.0f)
        #define CRV(R,G,B) (fmaf(-0.081312411f,(B), fmaf(-0.418687589f,(G), 0.5f*(R))) + 128.0f)
        #define CL(v) fminf(fmaxf((v), 0.0f), 255.0f)

        float y00 = CL(YV(r00,g00,b00)) - 128.0f;
        float y01 = CL(YV(r01,g01,b01)) - 128.0f;
        float y10 = CL(YV(r10,g10,b10)) - 128.0f;
        float y11 = CL(YV(r11,g11,b11)) - 128.0f;

        float cb00 = CL(CBV(r00,g00,b00)), cb01 = CL(CBV(r01,g01,b01));
        float cb10 = CL(CBV(r10,g10,b10)), cb11 = CL(CBV(r11,g11,b11));
        float cr00 = CL(CRV(r00,g00,b00)), cr01 = CL(CRV(r01,g01,b01));
        float cr10 = CL(CRV(r10,g10,b10)), cr11 = CL(CRV(r11,g11,b11));

        float cbm = 0.25f * (((cb00 + cb01) + cb10) + cb11) - 128.0f;
        float crm = 0.25f * (((cr00 + cr01) + cr10) + cr11) - 128.0f;

        *(float2*)&s_a[0][py][px]     = make_float2(y00, y01);
        *(float2*)&s_a[0][py+1][px]   = make_float2(y10, y11);
        float2 cbv = make_float2(cbm, cbm);
        float2 crv = make_float2(crm, crm);
        *(float2*)&s_a[1][py][px]     = cbv;
        *(float2*)&s_a[1][py+1][px]   = cbv;
        *(float2*)&s_a[2][py][px]     = crv;
        *(float2*)&s_a[2][py+1][px]   = crv;
    }
    __syncthreads();

    // ---- block/row assignment: 48 (channel, 8x8-block) units * 8 row-threads ----
    const int blk = tid >> 3;
    const int r   = tid & 7;
    const int c   = blk >> 4;
    const int rem = blk & 15;
    const int by  = rem >> 3;
    const int bx  = rem & 7;

    // ---- phase 3: DCT + quantize/dequantize ----
    float tmp[8];
    #pragma unroll
    for (int k = 0; k < 8; k++) tmp[k] = 0.0f;
    #pragma unroll
    for (int j = 0; j < 8; j++) {
        float d = s_d[r][j];
        const float4 x0 = *(const float4*)&s_a[c][by*8 + j][bx*8];
        const float4 x1 = *(const float4*)&s_a[c][by*8 + j][bx*8 + 4];
        tmp[0] = fmaf(d, x0.x, tmp[0]);  tmp[1] = fmaf(d, x0.y, tmp[1]);
        tmp[2] = fmaf(d, x0.z, tmp[2]);  tmp[3] = fmaf(d, x0.w, tmp[3]);
        tmp[4] = fmaf(d, x1.x, tmp[4]);  tmp[5] = fmaf(d, x1.y, tmp[5]);
        tmp[6] = fmaf(d, x1.z, tmp[6]);  tmp[7] = fmaf(d, x1.w, tmp[7]);
    }
    float dec[8];
    #pragma unroll
    for (int l = 0; l < 8; l++) {
        float acc = 0.0f;
        #pragma unroll
        for (int k = 0; k < 8; k++) acc = fmaf(tmp[k], s_d[l][k], acc);
        float q    = s_q[c][r][l];
        float comp = rintf(acc / q);
        dec[l]     = rintf(comp * q);
    }
    __syncthreads();
    *(float4*)&s_a[c][by*8 + r][bx*8]     = make_float4(dec[0], dec[1], dec[2], dec[3]);
    *(float4*)&s_a[c][by*8 + r][bx*8 + 4] = make_float4(dec[4], dec[5], dec[6], dec[7]);
    __syncthreads();

    // ---- phase 4: IDCT ----
    #pragma unroll
    for (int k = 0; k < 8; k++) tmp[k] = 0.0f;
    #pragma unroll
    for (int j = 0; j < 8; j++) {
        float d = s_d[j][r];
        const float4 x0 = *(const float4*)&s_a[c][by*8 + j][bx*8];
        const float4 x1 = *(const float4*)&s_a[c][by*8 + j][bx*8 + 4];
        tmp[0] = fmaf(d, x0.x, tmp[0]);  tmp[1] = fmaf(d, x0.y, tmp[1]);
        tmp[2] = fmaf(d, x0.z, tmp[2]);  tmp[3] = fmaf(d, x0.w, tmp[3]);
        tmp[4] = fmaf(d, x1.x, tmp[4]);  tmp[5] = fmaf(d, x1.y, tmp[5]);
        tmp[6] = fmaf(d, x1.z, tmp[6]);  tmp[7] = fmaf(d, x1.w, tmp[7]);
    }
    float zr[8];
    {
        const float off = (c == 0) ? 128.0f : 0.0f;
        #pragma unroll
        for (int l = 0; l < 8; l++) {
            float acc = 0.0f;
            #pragma unroll
            for (int k = 0; k < 8; k++) acc = fmaf(tmp[k], s_d[k][l], acc);
            zr[l] = acc + off;
        }
    }
    __syncthreads();
    *(float4*)&s_a[c][by*8 + r][bx*8]     = make_float4(zr[0], zr[1], zr[2], zr[3]);
    *(float4*)&s_a[c][by*8 + r][bx*8 + 4] = make_float4(zr[4], zr[5], zr[6], zr[7]);
    __syncthreads();

    // ---- phase 5: YCbCr -> RGB, clip, round, store (float4) ----
    if (tid < (TH * TW) / 4) {                   // 256 float4 slots
        const int py  = tid >> 4;
        const int px4 = (tid & 15) * 4;
        const float4 yv  = *(const float4*)&s_a[0][py][px4];
        const float4 cbv = *(const float4*)&s_a[1][py][px4];
        const float4 crv = *(const float4*)&s_a[2][py][px4];

        #define FIN(v) (rintf(fminf(fmaxf((v), 0.0f), 255.0f)) * (1.0f/255.0f))
        float4 R, G, Bv;
        R.x = FIN(fmaf(1.402f, crv.x, yv.x));  R.y = FIN(fmaf(1.402f, crv.y, yv.y));
        R.z = FIN(fmaf(1.402f, crv.z, yv.z));  R.w = FIN(fmaf(1.402f, crv.w, yv.w));
        G.x = FIN(fmaf(-0.714136286f, crv.x, fmaf(-0.344136286f, cbv.x, yv.x)));
        G.y = FIN(fmaf(-0.714136286f, crv.y, fmaf(-0.344136286f, cbv.y, yv.y)));
        G.z = FIN(fmaf(-0.714136286f, crv.z, fmaf(-0.344136286f, cbv.z, yv.z)));
        G.w = FIN(fmaf(-0.714136286f, crv.w, fmaf(-0.344136286f, cbv.w, yv.w)));
        Bv.x = FIN(fmaf(1.772f, cbv.x, yv.x)); Bv.y = FIN(fmaf(1.772f, cbv.y, yv.y));
        Bv.z = FIN(fmaf(1.772f, cbv.z, yv.z)); Bv.w = FIN(fmaf(1.772f, cbv.w, yv.w));

        const size_t idx = (size_t)(ty0 + py) * WIMG + (tx0 + px4);
        *(float4*)&obase[idx]           = R;
        *(float4*)&obase[plane + idx]   = G;
        *(float4*)&obase[2*plane + idx] = Bv;
    }
}

extern "C" void kernel_launch(void* const* d_in, const int* in_sizes, int n_in,
                              void* d_out, int out_size)
{
    const float* x = nullptr;
    const float* q = nullptr;
    const float* d = nullptr;
    int nimg = 0;
    for (int i = 0; i < n_in; i++) {
        if (in_sizes[i] == 192)      q = (const float*)d_in[i];
        else if (in_sizes[i] == 64)  d = (const float*)d_in[i];
        else { x = (const float*)d_in[i]; nimg = in_sizes[i] / (3 * HIMG * WIMG); }
    }
    dim3 grid(WIMG / TW, HIMG / TH, nimg);
    jpeg_kernel<<<grid, NT>>>(x, q, d, (float*)d_out);
}